// round 1
// baseline (speedup 1.0000x reference)
#include <cuda_runtime.h>
#include <cuda_bf16.h>
#include <math.h>

// Problem shape (fixed by the dataset)
#define Q 256
#define I 2048
#define D 256

#define SE_INV_TEMP 5.0f     // 1/0.2
#define BN_EPS 1e-5f

// ---------------- device scratch (no allocs allowed) ----------------
__device__ __align__(16) float g_W[Q * D];    // u_hat * a
__device__ __align__(16) float g_A2[Q * D];   // a*a
__device__ __align__(16) float g_AC2[Q * D];  // 2*a*c
__device__ __align__(16) float g_YG[I * D];   // normalized gallery
__device__ float g_b1[Q];                     // <u_hat, c>
__device__ float g_cc;                        // ||c||^2

// ---------------- block reduction (256 threads) ----------------
__device__ __forceinline__ float blockSum256(float v) {
    __shared__ float red[8];
    int lane = threadIdx.x & 31;
    int wid = threadIdx.x >> 5;
#pragma unroll
    for (int o = 16; o > 0; o >>= 1) v += __shfl_down_sync(0xffffffffu, v, o);
    __syncthreads();               // protect red[] reuse across calls
    if (lane == 0) red[wid] = v;
    __syncthreads();
    float s = 0.f;
#pragma unroll
    for (int i = 0; i < 8; ++i) s += red[i];
    return s;
}

// ---------------- preprocess: per-query (grid Q, block D) ----------------
__global__ void prep_q_kernel(const float* __restrict__ xq_in,
                              const float* __restrict__ yq_in,
                              const float* __restrict__ gamma,
                              const float* __restrict__ beta,
                              const float* __restrict__ mean,
                              const float* __restrict__ var) {
    int q = blockIdx.x;
    int d = threadIdx.x;

    float x = xq_in[q * D + d];
    float nx = sqrtf(blockSum256(x * x));
    float xn = x / fmaxf(nx, 1e-12f);
    float gate = 1.f / (1.f + __expf(-xn * SE_INV_TEMP));

    float istd = gamma[d] * rsqrtf(var[d] + BN_EPS);
    float c = beta[d] - mean[d] * istd;
    float a = gate * istd;

    float y = yq_in[q * D + d];
    float ny = sqrtf(blockSum256(y * y));
    float yn = y / fmaxf(ny, 1e-12f);

    float fq = fmaf(yn, a, c);
    float nf = sqrtf(blockSum256(fq * fq));
    float u = fq / fmaxf(nf, 1e-12f);

    g_W[q * D + d]   = u * a;
    g_A2[q * D + d]  = a * a;
    g_AC2[q * D + d] = 2.f * a * c;

    float b1 = blockSum256(u * c);
    if (d == 0) g_b1[q] = b1;

    if (q == 0) {                 // block-uniform branch
        float cc = blockSum256(c * c);
        if (d == 0) g_cc = cc;
    }
}

// ---------------- preprocess: gallery normalize (grid I, block D) ----------------
__global__ void prep_g_kernel(const float* __restrict__ yg) {
    int i = blockIdx.x;
    int d = threadIdx.x;
    float v = yg[i * D + d];
    float n = sqrtf(blockSum256(v * v));
    g_YG[i * D + d] = v / fmaxf(n, 1e-12f);
}

// ---------------- main: 3-way fused GEMM + sigmoid epilogue ----------------
// Block tile 64q x 64i, BK=32, 256 threads, 4x4 microtile per thread.
#define BQ 64
#define BI 64
#define BK 32
#define SPAD 68   // 64 + 4 pad: float4-aligned rows, <=4-way STS conflicts

__global__ __launch_bounds__(256) void score_kernel(float* __restrict__ out) {
    __shared__ __align__(16) float Ws[BK][SPAD];
    __shared__ __align__(16) float As[BK][SPAD];
    __shared__ __align__(16) float Cs[BK][SPAD];
    __shared__ __align__(16) float Ys[BK][SPAD];

    const int tid = threadIdx.x;
    const int tx = tid & 15;          // i direction
    const int ty = tid >> 4;          // q direction
    const int qb = blockIdx.y << 6;
    const int ib = blockIdx.x << 6;
    const int tq = ty << 2;
    const int ti = tx << 2;

    float num[16], den[16];
#pragma unroll
    for (int k = 0; k < 16; ++k) { num[k] = 0.f; den[k] = 0.f; }

    for (int k0 = 0; k0 < D; k0 += BK) {
        // coalesced float4 loads, transposed (k-major) stores
#pragma unroll
        for (int j = 0; j < 2; ++j) {
            int lin = (j << 8) + tid;          // 0..511
            int r = lin >> 3;                  // tile row 0..63
            int c4 = (lin & 7) << 2;           // k offset within chunk, 0..28

            float4 w4 = *(const float4*)(g_W + ((qb + r) << 8) + k0 + c4);
            Ws[c4 + 0][r] = w4.x; Ws[c4 + 1][r] = w4.y;
            Ws[c4 + 2][r] = w4.z; Ws[c4 + 3][r] = w4.w;

            float4 a4 = *(const float4*)(g_A2 + ((qb + r) << 8) + k0 + c4);
            As[c4 + 0][r] = a4.x; As[c4 + 1][r] = a4.y;
            As[c4 + 2][r] = a4.z; As[c4 + 3][r] = a4.w;

            float4 c4v = *(const float4*)(g_AC2 + ((qb + r) << 8) + k0 + c4);
            Cs[c4 + 0][r] = c4v.x; Cs[c4 + 1][r] = c4v.y;
            Cs[c4 + 2][r] = c4v.z; Cs[c4 + 3][r] = c4v.w;

            float4 y4 = *(const float4*)(g_YG + ((ib + r) << 8) + k0 + c4);
            Ys[c4 + 0][r] = y4.x; Ys[c4 + 1][r] = y4.y;
            Ys[c4 + 2][r] = y4.z; Ys[c4 + 3][r] = y4.w;
        }
        __syncthreads();

#pragma unroll 4
        for (int kk = 0; kk < BK; ++kk) {
            float4 wf = *(const float4*)&Ws[kk][tq];
            float4 af = *(const float4*)&As[kk][tq];
            float4 cf = *(const float4*)&Cs[kk][tq];
            float4 yf = *(const float4*)&Ys[kk][ti];
            float wa[4] = {wf.x, wf.y, wf.z, wf.w};
            float aa[4] = {af.x, af.y, af.z, af.w};
            float ca[4] = {cf.x, cf.y, cf.z, cf.w};
            float ya[4] = {yf.x, yf.y, yf.z, yf.w};
#pragma unroll
            for (int m = 0; m < 4; ++m) {
#pragma unroll
                for (int n = 0; n < 4; ++n) {
                    num[m * 4 + n] = fmaf(wa[m], ya[n], num[m * 4 + n]);
                    float t = fmaf(aa[m], ya[n], ca[m]);   // a^2*y + 2ac
                    den[m * 4 + n] = fmaf(t, ya[n], den[m * 4 + n]);
                }
            }
        }
        __syncthreads();
    }

    // epilogue: score = sigmoid( (num + b1) * rsqrt(den + cc) )
    const float cc = g_cc;
#pragma unroll
    for (int m = 0; m < 4; ++m) {
        const int qrow = qb + tq + m;
        const float b1v = g_b1[qrow];
        float r[4];
#pragma unroll
        for (int n = 0; n < 4; ++n) {
            float nm = num[m * 4 + n] + b1v;
            float dd = den[m * 4 + n] + cc;
            float cosv = nm * rsqrtf(fmaxf(dd, 1e-24f));
            r[n] = 1.f / (1.f + __expf(-cosv));
        }
        *(float4*)(out + (size_t)qrow * I + ib + ti) =
            make_float4(r[0], r[1], r[2], r[3]);
    }
}

// ---------------- entry ----------------
extern "C" void kernel_launch(void* const* d_in, const int* in_sizes, int n_in,
                              void* d_out, int out_size) {
    const float* query_feats      = (const float*)d_in[0];
    const float* query_img_feats  = (const float*)d_in[1];
    const float* gallery_img_feats= (const float*)d_in[2];
    const float* bn_gamma         = (const float*)d_in[3];
    const float* bn_beta          = (const float*)d_in[4];
    const float* bn_mean          = (const float*)d_in[5];
    const float* bn_var           = (const float*)d_in[6];
    float* out = (float*)d_out;

    prep_q_kernel<<<Q, D>>>(query_feats, query_img_feats,
                            bn_gamma, bn_beta, bn_mean, bn_var);
    prep_g_kernel<<<I, D>>>(gallery_img_feats);
    score_kernel<<<dim3(I / BI, Q / BQ), 256>>>(out);
}

// round 4
// speedup vs baseline: 1.2516x; 1.2516x over previous
#include <cuda_runtime.h>
#include <cuda_bf16.h>
#include <math.h>

// Problem shape (fixed by the dataset)
#define Q 256
#define I 2048
#define D 256

#define SE_INV_TEMP 5.0f     // 1/0.2
#define BN_EPS 1e-5f

// ---------------- device scratch (no allocs allowed) ----------------
__device__ __align__(16) float g_W[Q * D];    // u_hat * a
__device__ __align__(16) float g_A2[Q * D];   // a*a
__device__ __align__(16) float g_AC2[Q * D];  // 2*a*c
__device__ __align__(16) float g_YG[I * D];   // normalized gallery
__device__ float g_b1[Q];                     // <u_hat, c>
__device__ float g_cc;                        // ||c||^2

// ---------------- packed f32x2 helpers ----------------
__device__ __forceinline__ unsigned long long ffma2(unsigned long long a,
                                                    unsigned long long b,
                                                    unsigned long long c) {
    unsigned long long d;
    asm("fma.rn.f32x2 %0, %1, %2, %3;" : "=l"(d) : "l"(a), "l"(b), "l"(c));
    return d;
}
__device__ __forceinline__ float2 unpack2(unsigned long long v) {
    float2 r;
    asm("mov.b64 {%0, %1}, %2;" : "=f"(r.x), "=f"(r.y) : "l"(v));
    return r;
}

// ---------------- warp reduction ----------------
__device__ __forceinline__ float wsum(float v) {
#pragma unroll
    for (int o = 16; o > 0; o >>= 1) v += __shfl_xor_sync(0xffffffffu, v, o);
    return v;
}

// ---------------- fused preprocess: warp per row ----------------
// blocks 0..31: queries (8 per block). blocks 32..287: gallery rows (8 per block).
__global__ __launch_bounds__(256) void prep_kernel(
    const float* __restrict__ xq_in, const float* __restrict__ yq_in,
    const float* __restrict__ yg_in,
    const float* __restrict__ gamma, const float* __restrict__ beta,
    const float* __restrict__ mean,  const float* __restrict__ var) {
    const int lane = threadIdx.x & 31;
    const int warp = threadIdx.x >> 5;
    const int b = blockIdx.x;
    const int d0 = lane << 3;     // 8 elements per lane

    if (b < 32) {
        const int q = (b << 3) + warp;
        float x[8], y[8], a[8], c[8];
        // loads (2x float4 per array)
#pragma unroll
        for (int j = 0; j < 2; ++j) {
            float4 v = *(const float4*)(xq_in + (q << 8) + d0 + 4 * j);
            x[4*j+0]=v.x; x[4*j+1]=v.y; x[4*j+2]=v.z; x[4*j+3]=v.w;
            float4 w = *(const float4*)(yq_in + (q << 8) + d0 + 4 * j);
            y[4*j+0]=w.x; y[4*j+1]=w.y; y[4*j+2]=w.z; y[4*j+3]=w.w;
        }
        float gm[8], bt[8], mn[8], vr[8];
#pragma unroll
        for (int j = 0; j < 2; ++j) {
            float4 g4 = *(const float4*)(gamma + d0 + 4 * j);
            gm[4*j+0]=g4.x; gm[4*j+1]=g4.y; gm[4*j+2]=g4.z; gm[4*j+3]=g4.w;
            float4 b4 = *(const float4*)(beta + d0 + 4 * j);
            bt[4*j+0]=b4.x; bt[4*j+1]=b4.y; bt[4*j+2]=b4.z; bt[4*j+3]=b4.w;
            float4 m4 = *(const float4*)(mean + d0 + 4 * j);
            mn[4*j+0]=m4.x; mn[4*j+1]=m4.y; mn[4*j+2]=m4.z; mn[4*j+3]=m4.w;
            float4 v4 = *(const float4*)(var + d0 + 4 * j);
            vr[4*j+0]=v4.x; vr[4*j+1]=v4.y; vr[4*j+2]=v4.z; vr[4*j+3]=v4.w;
        }

        float sx = 0.f, sy = 0.f;
#pragma unroll
        for (int k = 0; k < 8; ++k) { sx = fmaf(x[k], x[k], sx); sy = fmaf(y[k], y[k], sy); }
        const float invx = 1.f / fmaxf(sqrtf(wsum(sx)), 1e-12f);
        const float invy = 1.f / fmaxf(sqrtf(wsum(sy)), 1e-12f);

        float fq[8];
        float sf = 0.f;
#pragma unroll
        for (int k = 0; k < 8; ++k) {
            float xn = x[k] * invx;
            float gate = 1.f / (1.f + __expf(-xn * SE_INV_TEMP));
            float istd = gm[k] * rsqrtf(vr[k] + BN_EPS);
            c[k] = bt[k] - mn[k] * istd;
            a[k] = gate * istd;
            float yn = y[k] * invy;
            fq[k] = fmaf(yn, a[k], c[k]);
            sf = fmaf(fq[k], fq[k], sf);
        }
        const float invf = 1.f / fmaxf(sqrtf(wsum(sf)), 1e-12f);

        float b1p = 0.f;
        float w_[8], a2_[8], c2_[8];
#pragma unroll
        for (int k = 0; k < 8; ++k) {
            float u = fq[k] * invf;
            w_[k]  = u * a[k];
            a2_[k] = a[k] * a[k];
            c2_[k] = 2.f * a[k] * c[k];
            b1p = fmaf(u, c[k], b1p);
        }
#pragma unroll
        for (int j = 0; j < 2; ++j) {
            *(float4*)(g_W  + (q << 8) + d0 + 4*j) = make_float4(w_[4*j], w_[4*j+1], w_[4*j+2], w_[4*j+3]);
            *(float4*)(g_A2 + (q << 8) + d0 + 4*j) = make_float4(a2_[4*j], a2_[4*j+1], a2_[4*j+2], a2_[4*j+3]);
            *(float4*)(g_AC2+ (q << 8) + d0 + 4*j) = make_float4(c2_[4*j], c2_[4*j+1], c2_[4*j+2], c2_[4*j+3]);
        }
        float b1 = wsum(b1p);
        if (lane == 0) g_b1[q] = b1;
        if (q == 0) {
            float ccp = 0.f;
#pragma unroll
            for (int k = 0; k < 8; ++k) ccp = fmaf(c[k], c[k], ccp);
            float cc = wsum(ccp);
            if (lane == 0) g_cc = cc;
        }
    } else {
        const int i = ((b - 32) << 3) + warp;
        float v[8];
        float s = 0.f;
#pragma unroll
        for (int j = 0; j < 2; ++j) {
            float4 v4 = *(const float4*)(yg_in + (i << 8) + d0 + 4 * j);
            v[4*j+0]=v4.x; v[4*j+1]=v4.y; v[4*j+2]=v4.z; v[4*j+3]=v4.w;
        }
#pragma unroll
        for (int k = 0; k < 8; ++k) s = fmaf(v[k], v[k], s);
        const float inv = 1.f / fmaxf(sqrtf(wsum(s)), 1e-12f);
#pragma unroll
        for (int j = 0; j < 2; ++j)
            *(float4*)(g_YG + (i << 8) + d0 + 4*j) =
                make_float4(v[4*j]*inv, v[4*j+1]*inv, v[4*j+2]*inv, v[4*j+3]*inv);
    }
}

// ---------------- main: packed-f32x2 fused GEMM + sigmoid epilogue ----------------
// Block tile 64q x 64i, BK=16, 256 threads, 4x4 microtile (i packed in pairs).
// q-side shared tiles stored pre-duplicated {v,v} so packed broadcasts come
// straight from LDS (warp-level broadcast, no mov.b64 packing in the hot loop).
#define BQ 64
#define BI 64
#define BK 16
#define WROW 132   // 2*BQ + 4 pad (528B rows, 16B aligned)
#define YROW 68    // BI + 4 pad (272B rows, 16B aligned)
#define NCHUNK (D / BK)

__global__ __launch_bounds__(256) void score_kernel(float* __restrict__ out) {
    __shared__ __align__(16) float Wd[BK][WROW];
    __shared__ __align__(16) float Ad[BK][WROW];
    __shared__ __align__(16) float Cd[BK][WROW];
    __shared__ __align__(16) float Ys[BK][YROW];

    const int tid = threadIdx.x;
    const int tx = tid & 15;          // i direction (4 i = 2 packed pairs)
    const int ty = tid >> 4;          // q direction (4 q)
    const int qb = blockIdx.y << 6;
    const int ib = blockIdx.x << 6;
    const int tq = ty << 2;
    const int ti = tx << 2;

    // loader mapping: one float4 per array per chunk
    const int lr = tid >> 2;                // tile row 0..63
    const int lc = (tid & 3) << 2;          // k offset 0,4,8,12
    const float* wp = g_W   + ((qb + lr) << 8) + lc;
    const float* ap = g_A2  + ((qb + lr) << 8) + lc;
    const float* cp = g_AC2 + ((qb + lr) << 8) + lc;
    const float* yp = g_YG  + ((ib + lr) << 8) + lc;

    unsigned long long num2[4][2], den2[4][2];
#pragma unroll
    for (int m = 0; m < 4; ++m)
#pragma unroll
        for (int p = 0; p < 2; ++p) { num2[m][p] = 0ull; den2[m][p] = 0ull; }

    // prefetch chunk 0
    float4 pw = *(const float4*)wp;
    float4 pa = *(const float4*)ap;
    float4 pc = *(const float4*)cp;
    float4 py = *(const float4*)yp;

    for (int ch = 0; ch < NCHUNK; ++ch) {
        // store prefetched chunk to shared (q-side duplicated)
        {
            float wv[4] = {pw.x, pw.y, pw.z, pw.w};
            float av[4] = {pa.x, pa.y, pa.z, pa.w};
            float cv[4] = {pc.x, pc.y, pc.z, pc.w};
            float yv[4] = {py.x, py.y, py.z, py.w};
#pragma unroll
            for (int t = 0; t < 4; ++t) {
                *(float2*)&Wd[lc + t][2 * lr] = make_float2(wv[t], wv[t]);
                *(float2*)&Ad[lc + t][2 * lr] = make_float2(av[t], av[t]);
                *(float2*)&Cd[lc + t][2 * lr] = make_float2(cv[t], cv[t]);
                Ys[lc + t][lr] = yv[t];
            }
        }
        __syncthreads();

        // prefetch next chunk (latency hidden by compute)
        if (ch + 1 < NCHUNK) {
            const int off = (ch + 1) << 4;
            pw = *(const float4*)(wp + off);
            pa = *(const float4*)(ap + off);
            pc = *(const float4*)(cp + off);
            py = *(const float4*)(yp + off);
        }

        // compute: 16 k steps, all packed f32x2
#pragma unroll
        for (int kk = 0; kk < BK; ++kk) {
            const ulonglong2 wA = *(const ulonglong2*)&Wd[kk][2 * tq];
            const ulonglong2 wB = *(const ulonglong2*)&Wd[kk][2 * tq + 4];
            const ulonglong2 aA = *(const ulonglong2*)&Ad[kk][2 * tq];
            const ulonglong2 aB = *(const ulonglong2*)&Ad[kk][2 * tq + 4];
            const ulonglong2 cA = *(const ulonglong2*)&Cd[kk][2 * tq];
            const ulonglong2 cB = *(const ulonglong2*)&Cd[kk][2 * tq + 4];
            const ulonglong2 yv = *(const ulonglong2*)&Ys[kk][ti];
            const unsigned long long wm[4] = {wA.x, wA.y, wB.x, wB.y};
            const unsigned long long am[4] = {aA.x, aA.y, aB.x, aB.y};
            const unsigned long long cm[4] = {cA.x, cA.y, cB.x, cB.y};
            const unsigned long long yq2[2] = {yv.x, yv.y};
#pragma unroll
            for (int m = 0; m < 4; ++m) {
#pragma unroll
                for (int p = 0; p < 2; ++p) {
                    num2[m][p] = ffma2(wm[m], yq2[p], num2[m][p]);
                    unsigned long long t = ffma2(am[m], yq2[p], cm[m]);
                    den2[m][p] = ffma2(t, yq2[p], den2[m][p]);
                }
            }
        }
        __syncthreads();
    }

    // epilogue: score = sigmoid( (num + b1) * rsqrt(den + cc) )
    const float cc = g_cc;
#pragma unroll
    for (int m = 0; m < 4; ++m) {
        const int qrow = qb + tq + m;
        const float b1v = g_b1[qrow];
        float2 n0 = unpack2(num2[m][0]);
        float2 n1 = unpack2(num2[m][1]);
        float2 d0 = unpack2(den2[m][0]);
        float2 d1 = unpack2(den2[m][1]);
        float nm[4] = {n0.x + b1v, n0.y + b1v, n1.x + b1v, n1.y + b1v};
        float dd[4] = {d0.x + cc,  d0.y + cc,  d1.x + cc,  d1.y + cc};
        float r[4];
#pragma unroll
        for (int n = 0; n < 4; ++n) {
            float cosv = nm[n] * rsqrtf(fmaxf(dd[n], 1e-24f));
            r[n] = 1.f / (1.f + __expf(-cosv));
        }
        *(float4*)(out + (size_t)qrow * I + ib + ti) =
            make_float4(r[0], r[1], r[2], r[3]);
    }
}

// ---------------- entry ----------------
extern "C" void kernel_launch(void* const* d_in, const int* in_sizes, int n_in,
                              void* d_out, int out_size) {
    const float* query_feats      = (const float*)d_in[0];
    const float* query_img_feats  = (const float*)d_in[1];
    const float* gallery_img_feats= (const float*)d_in[2];
    const float* bn_gamma         = (const float*)d_in[3];
    const float* bn_beta          = (const float*)d_in[4];
    const float* bn_mean          = (const float*)d_in[5];
    const float* bn_var           = (const float*)d_in[6];
    float* out = (float*)d_out;

    prep_kernel<<<288, 256>>>(query_feats, query_img_feats, gallery_img_feats,
                              bn_gamma, bn_beta, bn_mean, bn_var);
    score_kernel<<<dim3(I / BI, Q / BQ), 256>>>(out);
}

// round 11
// speedup vs baseline: 2.9231x; 2.3355x over previous
#include <cuda_runtime.h>
#include <cuda_bf16.h>
#include <math.h>
#include <cstdint>

// Problem shape (fixed by the dataset)
#define Q 256
#define I 2048
#define D 256

#define SE_INV_TEMP 5.0f     // 1/0.2
#define BN_EPS 1e-5f

// ---------------- device scratch (no allocs allowed) ----------------
__device__ __align__(16) __nv_bfloat16 g_Wb[Q * D];    // u_hat * a
__device__ __align__(16) __nv_bfloat16 g_A2b[Q * D];   // a*a
__device__ __align__(16) __nv_bfloat16 g_C2b[Q * D];   // 2*a*c
__device__ __align__(16) __nv_bfloat16 g_Yb[I * D];    // normalized gallery y
__device__ __align__(16) __nv_bfloat16 g_Y2b[I * D];   // y*y
__device__ float g_b1[Q];                              // <u_hat, c>
__device__ float g_cc;                                 // ||c||^2

// ---------------- PTX helpers (sm_80-era ops only: legal on compute_103) ----
__device__ __forceinline__ void cp16(uint32_t dst, const void* src) {
    asm volatile("cp.async.ca.shared.global [%0], [%1], 16;"
                 :: "r"(dst), "l"(src));
}
#define CP_COMMIT() asm volatile("cp.async.commit_group;" ::: "memory")
#define CP_WAIT(n)  asm volatile("cp.async.wait_group %0;" :: "n"(n) : "memory")

__device__ __forceinline__ void ldmx4(uint32_t* r, uint32_t a) {
    asm volatile("ldmatrix.sync.aligned.m8n8.x4.shared.b16 {%0,%1,%2,%3}, [%4];"
                 : "=r"(r[0]), "=r"(r[1]), "=r"(r[2]), "=r"(r[3]) : "r"(a));
}

__device__ __forceinline__ void mma16816(float* d, const uint32_t* a,
                                         const uint32_t* b) {
    asm volatile(
        "mma.sync.aligned.m16n8k16.row.col.f32.bf16.bf16.f32 "
        "{%0,%1,%2,%3}, {%4,%5,%6,%7}, {%8,%9}, {%0,%1,%2,%3};"
        : "+f"(d[0]), "+f"(d[1]), "+f"(d[2]), "+f"(d[3])
        : "r"(a[0]), "r"(a[1]), "r"(a[2]), "r"(a[3]), "r"(b[0]), "r"(b[1]));
}

// ---------------- warp reduction ----------------
__device__ __forceinline__ float wsum(float v) {
#pragma unroll
    for (int o = 16; o > 0; o >>= 1) v += __shfl_xor_sync(0xffffffffu, v, o);
    return v;
}

__device__ __forceinline__ uint4 pack8_bf16(const float* v) {
    __nv_bfloat162 a = __floats2bfloat162_rn(v[0], v[1]);
    __nv_bfloat162 b = __floats2bfloat162_rn(v[2], v[3]);
    __nv_bfloat162 c = __floats2bfloat162_rn(v[4], v[5]);
    __nv_bfloat162 d = __floats2bfloat162_rn(v[6], v[7]);
    uint4 r;
    r.x = *(unsigned*)&a; r.y = *(unsigned*)&b;
    r.z = *(unsigned*)&c; r.w = *(unsigned*)&d;
    return r;
}

// ---------------- fused preprocess: warp per row ----------------
// blocks 0..31: queries (8 per block). blocks 32..287: gallery rows (8 per block).
__global__ __launch_bounds__(256) void prep_kernel(
    const float* __restrict__ xq_in, const float* __restrict__ yq_in,
    const float* __restrict__ yg_in,
    const float* __restrict__ gamma, const float* __restrict__ beta,
    const float* __restrict__ mean,  const float* __restrict__ var) {
    const int lane = threadIdx.x & 31;
    const int warp = threadIdx.x >> 5;
    const int b = blockIdx.x;
    const int d0 = lane << 3;     // 8 elements per lane

    if (b < 32) {
        const int q = (b << 3) + warp;
        float x[8], y[8], a[8], c[8];
#pragma unroll
        for (int j = 0; j < 2; ++j) {
            float4 v = *(const float4*)(xq_in + (q << 8) + d0 + 4 * j);
            x[4*j+0]=v.x; x[4*j+1]=v.y; x[4*j+2]=v.z; x[4*j+3]=v.w;
            float4 w = *(const float4*)(yq_in + (q << 8) + d0 + 4 * j);
            y[4*j+0]=w.x; y[4*j+1]=w.y; y[4*j+2]=w.z; y[4*j+3]=w.w;
        }
        float gm[8], bt[8], mn[8], vr[8];
#pragma unroll
        for (int j = 0; j < 2; ++j) {
            float4 g4 = *(const float4*)(gamma + d0 + 4 * j);
            gm[4*j+0]=g4.x; gm[4*j+1]=g4.y; gm[4*j+2]=g4.z; gm[4*j+3]=g4.w;
            float4 b4 = *(const float4*)(beta + d0 + 4 * j);
            bt[4*j+0]=b4.x; bt[4*j+1]=b4.y; bt[4*j+2]=b4.z; bt[4*j+3]=b4.w;
            float4 m4 = *(const float4*)(mean + d0 + 4 * j);
            mn[4*j+0]=m4.x; mn[4*j+1]=m4.y; mn[4*j+2]=m4.z; mn[4*j+3]=m4.w;
            float4 v4 = *(const float4*)(var + d0 + 4 * j);
            vr[4*j+0]=v4.x; vr[4*j+1]=v4.y; vr[4*j+2]=v4.z; vr[4*j+3]=v4.w;
        }

        float sx = 0.f, sy = 0.f;
#pragma unroll
        for (int k = 0; k < 8; ++k) { sx = fmaf(x[k], x[k], sx); sy = fmaf(y[k], y[k], sy); }
        const float invx = 1.f / fmaxf(sqrtf(wsum(sx)), 1e-12f);
        const float invy = 1.f / fmaxf(sqrtf(wsum(sy)), 1e-12f);

        float fq[8];
        float sf = 0.f;
#pragma unroll
        for (int k = 0; k < 8; ++k) {
            float xn = x[k] * invx;
            float gate = 1.f / (1.f + __expf(-xn * SE_INV_TEMP));
            float istd = gm[k] * rsqrtf(vr[k] + BN_EPS);
            c[k] = bt[k] - mn[k] * istd;
            a[k] = gate * istd;
            float yn = y[k] * invy;
            fq[k] = fmaf(yn, a[k], c[k]);
            sf = fmaf(fq[k], fq[k], sf);
        }
        const float invf = 1.f / fmaxf(sqrtf(wsum(sf)), 1e-12f);

        float b1p = 0.f;
        float w_[8], a2_[8], c2_[8];
#pragma unroll
        for (int k = 0; k < 8; ++k) {
            float u = fq[k] * invf;
            w_[k]  = u * a[k];
            a2_[k] = a[k] * a[k];
            c2_[k] = 2.f * a[k] * c[k];
            b1p = fmaf(u, c[k], b1p);
        }
        *(uint4*)(g_Wb  + (q << 8) + d0) = pack8_bf16(w_);
        *(uint4*)(g_A2b + (q << 8) + d0) = pack8_bf16(a2_);
        *(uint4*)(g_C2b + (q << 8) + d0) = pack8_bf16(c2_);

        float b1 = wsum(b1p);
        if (lane == 0) g_b1[q] = b1;
        if (q == 0) {
            float ccp = 0.f;
#pragma unroll
            for (int k = 0; k < 8; ++k) ccp = fmaf(c[k], c[k], ccp);
            float cc = wsum(ccp);
            if (lane == 0) g_cc = cc;
        }
    } else {
        const int i = ((b - 32) << 3) + warp;
        float v[8];
        float s = 0.f;
#pragma unroll
        for (int j = 0; j < 2; ++j) {
            float4 v4 = *(const float4*)(yg_in + (i << 8) + d0 + 4 * j);
            v[4*j+0]=v4.x; v[4*j+1]=v4.y; v[4*j+2]=v4.z; v[4*j+3]=v4.w;
        }
#pragma unroll
        for (int k = 0; k < 8; ++k) s = fmaf(v[k], v[k], s);
        const float inv = 1.f / fmaxf(sqrtf(wsum(s)), 1e-12f);
        float yn[8], y2[8];
#pragma unroll
        for (int k = 0; k < 8; ++k) { yn[k] = v[k] * inv; y2[k] = yn[k] * yn[k]; }
        *(uint4*)(g_Yb  + (i << 8) + d0) = pack8_bf16(yn);
        *(uint4*)(g_Y2b + (i << 8) + d0) = pack8_bf16(y2);
    }
}

// ---------------- main: HMMA (mma.sync bf16) triple-GEMM + sigmoid ------------
// CTA tile 64q x 64i, grid 32x4 = 128 CTAs (one wave).
// 8 warps: wm in {0,1} (32 q-rows), wn in {0..3} (16 i-cols). Warp tile 32x16.
// K chunked by 32 (8 chunks), cp.async double-buffered, DYNAMIC smem.
// Row stride 80B: 16B-aligned (cp.async-legal) and conflict-free for ldmatrix
// (80*r mod 128, r=0..7 -> {0,80,32,112,64,16,96,48}: all 16B slots distinct).
#define BK 32
#define NCH (D / BK)          // 8
#define SRL 80                // row stride bytes (16B-aligned, conflict-free)
#define MATB (64 * SRL)       // 5120
#define BUFB (5 * MATB)       // 25600
#define SMEM_SCORE (2 * BUFB) // 51200

__global__ __launch_bounds__(256) void score_kernel(float* __restrict__ out) {
    extern __shared__ __align__(16) char smem[];

    const int tid = threadIdx.x;
    const int wid = tid >> 5;
    const int lane = tid & 31;
    const int wm = wid & 1;
    const int wn = wid >> 1;
    const int qb = blockIdx.y << 6;
    const int ib = blockIdx.x << 6;

    const uint32_t sb0 = (uint32_t)__cvta_generic_to_shared(&smem[0]);

    // cp.async mapping: each thread moves one 16B unit per matrix per chunk
    const int lrowG = tid >> 2;           // 0..63
    const int lcG = tid & 3;              // 0..3
    const uint32_t dstBase = sb0 + lrowG * SRL + lcG * 16;
    const int srcOffBase = lrowG * D + lcG * 8;

#define LOAD_CHUNK(ch, bb) do {                                              \
        const int kc_ = (ch) << 5;                                           \
        uint32_t d_ = dstBase + (bb) * BUFB;                                 \
        const int so_ = srcOffBase + kc_;                                    \
        cp16(d_ + 0 * MATB, g_Wb  + qb * D + so_);                           \
        cp16(d_ + 1 * MATB, g_A2b + qb * D + so_);                           \
        cp16(d_ + 2 * MATB, g_C2b + qb * D + so_);                           \
        cp16(d_ + 3 * MATB, g_Yb  + ib * D + so_);                           \
        cp16(d_ + 4 * MATB, g_Y2b + ib * D + so_);                           \
    } while (0)

    // ldmatrix per-lane addresses (buffer 0, k-step 0)
    const int lrow = ((lane >> 3) & 1) * 8 + (lane & 7);
    const int kb = ((lane >> 4) & 1) * 16;
    uint32_t adW[2], adA[2], adC[2];
#pragma unroll
    for (int mt = 0; mt < 2; ++mt) {
        const int r = wm * 32 + mt * 16 + lrow;
        adW[mt] = sb0 + 0 * MATB + r * SRL + kb;
        adA[mt] = sb0 + 1 * MATB + r * SRL + kb;
        adC[mt] = sb0 + 2 * MATB + r * SRL + kb;
    }
    const int rB = wn * 16 + lrow;
    const uint32_t adY  = sb0 + 3 * MATB + rB * SRL + kb;
    const uint32_t adY2 = sb0 + 4 * MATB + rB * SRL + kb;

    float num[2][2][4], den[2][2][4];
#pragma unroll
    for (int mt = 0; mt < 2; ++mt)
#pragma unroll
        for (int nt = 0; nt < 2; ++nt)
#pragma unroll
            for (int k = 0; k < 4; ++k) { num[mt][nt][k] = 0.f; den[mt][nt][k] = 0.f; }

    LOAD_CHUNK(0, 0);
    CP_COMMIT();

    for (int ch = 0; ch < NCH; ++ch) {
        const int b = ch & 1;
        if (ch < NCH - 1) {
            LOAD_CHUNK(ch + 1, b ^ 1);
            CP_COMMIT();
            CP_WAIT(1);
        } else {
            CP_WAIT(0);
        }
        __syncthreads();

        const uint32_t boff = b * BUFB;
#pragma unroll
        for (int kk = 0; kk < 2; ++kk) {
            const uint32_t ko = boff + kk * 32;
            uint32_t w0[4], w1[4], a0[4], a1[4], c0[4], c1[4], y[4], y2[4];
            ldmx4(w0, adW[0] + ko); ldmx4(w1, adW[1] + ko);
            ldmx4(a0, adA[0] + ko); ldmx4(a1, adA[1] + ko);
            ldmx4(c0, adC[0] + ko); ldmx4(c1, adC[1] + ko);
            ldmx4(y,  adY  + ko);   ldmx4(y2, adY2 + ko);
            uint32_t Y0[2] = {y[0],  y[2]},  Y1[2] = {y[1],  y[3]};
            uint32_t Z0[2] = {y2[0], y2[2]}, Z1[2] = {y2[1], y2[3]};

            mma16816(num[0][0], w0, Y0); mma16816(num[0][1], w0, Y1);
            mma16816(num[1][0], w1, Y0); mma16816(num[1][1], w1, Y1);
            mma16816(den[0][0], a0, Z0); mma16816(den[0][1], a0, Z1);
            mma16816(den[1][0], a1, Z0); mma16816(den[1][1], a1, Z1);
            mma16816(den[0][0], c0, Y0); mma16816(den[0][1], c0, Y1);
            mma16816(den[1][0], c1, Y0); mma16816(den[1][1], c1, Y1);
        }
        __syncthreads();
    }

    // epilogue: score = sigmoid( (num + b1[q]) * rsqrt(den + cc) )
    const float ccv = g_cc;
#pragma unroll
    for (int mt = 0; mt < 2; ++mt) {
        const int r0 = qb + wm * 32 + mt * 16 + (lane >> 2);
        const float b1a = g_b1[r0];
        const float b1b = g_b1[r0 + 8];
#pragma unroll
        for (int nt = 0; nt < 2; ++nt) {
            const int col = ib + wn * 16 + nt * 8 + ((lane & 3) << 1);
            const float* d = num[mt][nt];
            const float* e = den[mt][nt];
            float v0 = (d[0] + b1a) * rsqrtf(fmaxf(e[0] + ccv, 1e-24f));
            float v1 = (d[1] + b1a) * rsqrtf(fmaxf(e[1] + ccv, 1e-24f));
            float v2 = (d[2] + b1b) * rsqrtf(fmaxf(e[2] + ccv, 1e-24f));
            float v3 = (d[3] + b1b) * rsqrtf(fmaxf(e[3] + ccv, 1e-24f));
            float2 p0, p1;
            p0.x = 1.f / (1.f + __expf(-v0));
            p0.y = 1.f / (1.f + __expf(-v1));
            p1.x = 1.f / (1.f + __expf(-v2));
            p1.y = 1.f / (1.f + __expf(-v3));
            *(float2*)(out + (size_t)r0 * I + col) = p0;
            *(float2*)(out + (size_t)(r0 + 8) * I + col) = p1;
        }
    }
}

// ---------------- entry ----------------
extern "C" void kernel_launch(void* const* d_in, const int* in_sizes, int n_in,
                              void* d_out, int out_size) {
    const float* query_feats      = (const float*)d_in[0];
    const float* query_img_feats  = (const float*)d_in[1];
    const float* gallery_img_feats= (const float*)d_in[2];
    const float* bn_gamma         = (const float*)d_in[3];
    const float* bn_beta          = (const float*)d_in[4];
    const float* bn_mean          = (const float*)d_in[5];
    const float* bn_var           = (const float*)d_in[6];
    float* out = (float*)d_out;

    cudaFuncSetAttribute(score_kernel,
                         cudaFuncAttributeMaxDynamicSharedMemorySize, SMEM_SCORE);

    prep_kernel<<<288, 256>>>(query_feats, query_img_feats, gallery_img_feats,
                              bn_gamma, bn_beta, bn_mean, bn_var);
    score_kernel<<<dim3(I / 64, Q / 64), 256, SMEM_SCORE>>>(out);
}

// round 13
// speedup vs baseline: 3.2264x; 1.1038x over previous
#include <cuda_runtime.h>
#include <cuda_bf16.h>
#include <math.h>
#include <cstdint>

// Problem shape (fixed by the dataset)
#define Q 256
#define I 2048
#define D 256

#define SE_INV_TEMP 5.0f     // 1/0.2
#define BN_EPS 1e-5f

// ---------------- device scratch (no allocs allowed) ----------------
__device__ __align__(16) __nv_bfloat16 g_Wb[Q * D];    // u_hat * a
__device__ __align__(16) __nv_bfloat16 g_A2b[Q * D];   // a*a
__device__ __align__(16) __nv_bfloat16 g_C2b[Q * D];   // 2*a*c
__device__ __align__(16) __nv_bfloat16 g_Yb[I * D];    // normalized gallery y
__device__ __align__(16) __nv_bfloat16 g_Y2b[I * D];   // y*y
__device__ float g_b1[Q];                              // <u_hat, c>
__device__ float g_cc;                                 // ||c||^2

// ---------------- PTX helpers (sm_80-era ops only: legal on compute_103) ----
__device__ __forceinline__ void cp16(uint32_t dst, const void* src) {
    asm volatile("cp.async.ca.shared.global [%0], [%1], 16;"
                 :: "r"(dst), "l"(src));
}
#define CP_COMMIT() asm volatile("cp.async.commit_group;" ::: "memory")
#define CP_WAIT(n)  asm volatile("cp.async.wait_group %0;" :: "n"(n) : "memory")

__device__ __forceinline__ void ldmx4(uint32_t* r, uint32_t a) {
    asm volatile("ldmatrix.sync.aligned.m8n8.x4.shared.b16 {%0,%1,%2,%3}, [%4];"
                 : "=r"(r[0]), "=r"(r[1]), "=r"(r[2]), "=r"(r[3]) : "r"(a));
}

__device__ __forceinline__ void mma16816(float* d, const uint32_t* a,
                                         const uint32_t* b) {
    asm volatile(
        "mma.sync.aligned.m16n8k16.row.col.f32.bf16.bf16.f32 "
        "{%0,%1,%2,%3}, {%4,%5,%6,%7}, {%8,%9}, {%0,%1,%2,%3};"
        : "+f"(d[0]), "+f"(d[1]), "+f"(d[2]), "+f"(d[3])
        : "r"(a[0]), "r"(a[1]), "r"(a[2]), "r"(a[3]), "r"(b[0]), "r"(b[1]));
}

// ---------------- warp reduction ----------------
__device__ __forceinline__ float wsum(float v) {
#pragma unroll
    for (int o = 16; o > 0; o >>= 1) v += __shfl_xor_sync(0xffffffffu, v, o);
    return v;
}

__device__ __forceinline__ uint4 pack8_bf16(const float* v) {
    __nv_bfloat162 a = __floats2bfloat162_rn(v[0], v[1]);
    __nv_bfloat162 b = __floats2bfloat162_rn(v[2], v[3]);
    __nv_bfloat162 c = __floats2bfloat162_rn(v[4], v[5]);
    __nv_bfloat162 d = __floats2bfloat162_rn(v[6], v[7]);
    uint4 r;
    r.x = *(unsigned*)&a; r.y = *(unsigned*)&b;
    r.z = *(unsigned*)&c; r.w = *(unsigned*)&d;
    return r;
}

// ---------------- fused preprocess: warp per row ----------------
// blocks 0..31: queries (8 per block). blocks 32..287: gallery rows (8 per block).
__global__ __launch_bounds__(256) void prep_kernel(
    const float* __restrict__ xq_in, const float* __restrict__ yq_in,
    const float* __restrict__ yg_in,
    const float* __restrict__ gamma, const float* __restrict__ beta,
    const float* __restrict__ mean,  const float* __restrict__ var) {
    const int lane = threadIdx.x & 31;
    const int warp = threadIdx.x >> 5;
    const int b = blockIdx.x;
    const int d0 = lane << 3;     // 8 elements per lane

    if (b < 32) {
        const int q = (b << 3) + warp;
        float x[8], y[8], a[8], c[8];
#pragma unroll
        for (int j = 0; j < 2; ++j) {
            float4 v = *(const float4*)(xq_in + (q << 8) + d0 + 4 * j);
            x[4*j+0]=v.x; x[4*j+1]=v.y; x[4*j+2]=v.z; x[4*j+3]=v.w;
            float4 w = *(const float4*)(yq_in + (q << 8) + d0 + 4 * j);
            y[4*j+0]=w.x; y[4*j+1]=w.y; y[4*j+2]=w.z; y[4*j+3]=w.w;
        }
        float gm[8], bt[8], mn[8], vr[8];
#pragma unroll
        for (int j = 0; j < 2; ++j) {
            float4 g4 = *(const float4*)(gamma + d0 + 4 * j);
            gm[4*j+0]=g4.x; gm[4*j+1]=g4.y; gm[4*j+2]=g4.z; gm[4*j+3]=g4.w;
            float4 b4 = *(const float4*)(beta + d0 + 4 * j);
            bt[4*j+0]=b4.x; bt[4*j+1]=b4.y; bt[4*j+2]=b4.z; bt[4*j+3]=b4.w;
            float4 m4 = *(const float4*)(mean + d0 + 4 * j);
            mn[4*j+0]=m4.x; mn[4*j+1]=m4.y; mn[4*j+2]=m4.z; mn[4*j+3]=m4.w;
            float4 v4 = *(const float4*)(var + d0 + 4 * j);
            vr[4*j+0]=v4.x; vr[4*j+1]=v4.y; vr[4*j+2]=v4.z; vr[4*j+3]=v4.w;
        }

        float sx = 0.f, sy = 0.f;
#pragma unroll
        for (int k = 0; k < 8; ++k) { sx = fmaf(x[k], x[k], sx); sy = fmaf(y[k], y[k], sy); }
        const float invx = 1.f / fmaxf(sqrtf(wsum(sx)), 1e-12f);
        const float invy = 1.f / fmaxf(sqrtf(wsum(sy)), 1e-12f);

        float fq[8];
        float sf = 0.f;
#pragma unroll
        for (int k = 0; k < 8; ++k) {
            float xn = x[k] * invx;
            float gate = 1.f / (1.f + __expf(-xn * SE_INV_TEMP));
            float istd = gm[k] * rsqrtf(vr[k] + BN_EPS);
            c[k] = bt[k] - mn[k] * istd;
            a[k] = gate * istd;
            float yn = y[k] * invy;
            fq[k] = fmaf(yn, a[k], c[k]);
            sf = fmaf(fq[k], fq[k], sf);
        }
        const float invf = 1.f / fmaxf(sqrtf(wsum(sf)), 1e-12f);

        float b1p = 0.f;
        float w_[8], a2_[8], c2_[8];
#pragma unroll
        for (int k = 0; k < 8; ++k) {
            float u = fq[k] * invf;
            w_[k]  = u * a[k];
            a2_[k] = a[k] * a[k];
            c2_[k] = 2.f * a[k] * c[k];
            b1p = fmaf(u, c[k], b1p);
        }
        *(uint4*)(g_Wb  + (q << 8) + d0) = pack8_bf16(w_);
        *(uint4*)(g_A2b + (q << 8) + d0) = pack8_bf16(a2_);
        *(uint4*)(g_C2b + (q << 8) + d0) = pack8_bf16(c2_);

        float b1 = wsum(b1p);
        if (lane == 0) g_b1[q] = b1;
        if (q == 0) {
            float ccp = 0.f;
#pragma unroll
            for (int k = 0; k < 8; ++k) ccp = fmaf(c[k], c[k], ccp);
            float cc = wsum(ccp);
            if (lane == 0) g_cc = cc;
        }
    } else {
        const int i = ((b - 32) << 3) + warp;
        float v[8];
        float s = 0.f;
#pragma unroll
        for (int j = 0; j < 2; ++j) {
            float4 v4 = *(const float4*)(yg_in + (i << 8) + d0 + 4 * j);
            v[4*j+0]=v4.x; v[4*j+1]=v4.y; v[4*j+2]=v4.z; v[4*j+3]=v4.w;
        }
#pragma unroll
        for (int k = 0; k < 8; ++k) s = fmaf(v[k], v[k], s);
        const float inv = 1.f / fmaxf(sqrtf(wsum(s)), 1e-12f);
        float yn[8], y2[8];
#pragma unroll
        for (int k = 0; k < 8; ++k) { yn[k] = v[k] * inv; y2[k] = yn[k] * yn[k]; }
        *(uint4*)(g_Yb  + (i << 8) + d0) = pack8_bf16(yn);
        *(uint4*)(g_Y2b + (i << 8) + d0) = pack8_bf16(y2);
    }
}

// ---------------- main: HMMA (mma.sync bf16) triple-GEMM + sigmoid ------------
// CTA tile 64q x 64i, grid 32x4 = 128 CTAs (one wave).
// 8 warps: wm in {0,1} (32 q-rows), wn in {0..3} (16 i-cols). Warp tile 32x16.
// K split into 4 chunks of 64, each in its OWN smem buffer (no reuse, no WAR
// barriers). All 4 cp.async groups are issued upfront (full-depth prefetch);
// consumption uses progressive wait_group 3/2/1/0 + one barrier per chunk.
// Row stride 144B: 16B-aligned (cp.async) and conflict-free for ldmatrix
// (r*144 mod 128 = r*16 -> 8 distinct 16B slots).
#define BK 64
#define NCH (D / BK)            // 4
#define SRL 144                 // row stride bytes
#define MATB (64 * SRL)         // 9216
#define BUFB (5 * MATB)         // 46080
#define SMEM_SCORE (NCH * BUFB) // 184320

__global__ __launch_bounds__(256) void score_kernel(float* __restrict__ out) {
    extern __shared__ __align__(16) char smem[];

    const int tid = threadIdx.x;
    const int wid = tid >> 5;
    const int lane = tid & 31;
    const int wm = wid & 1;
    const int wn = wid >> 1;
    const int qb = blockIdx.y << 6;
    const int ib = blockIdx.x << 6;

    const uint32_t sb0 = (uint32_t)__cvta_generic_to_shared(&smem[0]);

    // cp.async mapping: 512 16B-units per matrix per chunk, 2 per thread.
    // unit u: row = u>>3 (0..63), c16 = u&7 (16B slot within the 128B of data)
    const int u0 = tid, u1 = tid + 256;
    const int r0_ = u0 >> 3, c0_ = u0 & 7;
    const int r1_ = u1 >> 3, c1_ = u1 & 7;

#define LOAD_CHUNK(ch) do {                                                   \
        const int kc_ = (ch) * BK;                                            \
        const uint32_t db_ = sb0 + (ch) * BUFB;                               \
        const uint32_t dA_ = db_ + r0_ * SRL + c0_ * 16;                      \
        const uint32_t dB_ = db_ + r1_ * SRL + c1_ * 16;                      \
        const int sA_ = r0_ * D + kc_ + c0_ * 8;                              \
        const int sB_ = r1_ * D + kc_ + c1_ * 8;                              \
        cp16(dA_ + 0 * MATB, g_Wb  + qb * D + sA_);                           \
        cp16(dB_ + 0 * MATB, g_Wb  + qb * D + sB_);                           \
        cp16(dA_ + 1 * MATB, g_A2b + qb * D + sA_);                           \
        cp16(dB_ + 1 * MATB, g_A2b + qb * D + sB_);                           \
        cp16(dA_ + 2 * MATB, g_C2b + qb * D + sA_);                           \
        cp16(dB_ + 2 * MATB, g_C2b + qb * D + sB_);                           \
        cp16(dA_ + 3 * MATB, g_Yb  + ib * D + sA_);                           \
        cp16(dB_ + 3 * MATB, g_Yb  + ib * D + sB_);                           \
        cp16(dA_ + 4 * MATB, g_Y2b + ib * D + sA_);                           \
        cp16(dB_ + 4 * MATB, g_Y2b + ib * D + sB_);                           \
    } while (0)

    LOAD_CHUNK(0); CP_COMMIT();
    LOAD_CHUNK(1); CP_COMMIT();
    LOAD_CHUNK(2); CP_COMMIT();
    LOAD_CHUNK(3); CP_COMMIT();

    // ldmatrix per-lane base addresses (chunk 0, k-step 0)
    const int lrow = ((lane >> 3) & 1) * 8 + (lane & 7);
    const int kb = ((lane >> 4) & 1) * 16;
    uint32_t adW[2], adA[2], adC[2];
#pragma unroll
    for (int mt = 0; mt < 2; ++mt) {
        const int r = wm * 32 + mt * 16 + lrow;
        adW[mt] = sb0 + 0 * MATB + r * SRL + kb;
        adA[mt] = sb0 + 1 * MATB + r * SRL + kb;
        adC[mt] = sb0 + 2 * MATB + r * SRL + kb;
    }
    const int rB = wn * 16 + lrow;
    const uint32_t adY  = sb0 + 3 * MATB + rB * SRL + kb;
    const uint32_t adY2 = sb0 + 4 * MATB + rB * SRL + kb;

    float num[2][2][4], den[2][2][4];
#pragma unroll
    for (int mt = 0; mt < 2; ++mt)
#pragma unroll
        for (int nt = 0; nt < 2; ++nt)
#pragma unroll
            for (int k = 0; k < 4; ++k) { num[mt][nt][k] = 0.f; den[mt][nt][k] = 0.f; }

#pragma unroll
    for (int ch = 0; ch < NCH; ++ch) {
        // progressive drain: chunk ch ready when <= (NCH-1-ch) groups pending
        if      (ch == 0) CP_WAIT(3);
        else if (ch == 1) CP_WAIT(2);
        else if (ch == 2) CP_WAIT(1);
        else              CP_WAIT(0);
        __syncthreads();   // cross-thread visibility of cp.async fills

        const uint32_t boff = ch * BUFB;
#pragma unroll
        for (int kk = 0; kk < 4; ++kk) {
            const uint32_t ko = boff + kk * 32;
            uint32_t w0[4], w1[4], a0[4], a1[4], c0[4], c1[4], y[4], y2[4];
            ldmx4(w0, adW[0] + ko); ldmx4(w1, adW[1] + ko);
            ldmx4(a0, adA[0] + ko); ldmx4(a1, adA[1] + ko);
            ldmx4(c0, adC[0] + ko); ldmx4(c1, adC[1] + ko);
            ldmx4(y,  adY  + ko);   ldmx4(y2, adY2 + ko);
            uint32_t Y0[2] = {y[0],  y[2]},  Y1[2] = {y[1],  y[3]};
            uint32_t Z0[2] = {y2[0], y2[2]}, Z1[2] = {y2[1], y2[3]};

            mma16816(num[0][0], w0, Y0); mma16816(num[0][1], w0, Y1);
            mma16816(num[1][0], w1, Y0); mma16816(num[1][1], w1, Y1);
            mma16816(den[0][0], a0, Z0); mma16816(den[0][1], a0, Z1);
            mma16816(den[1][0], a1, Z0); mma16816(den[1][1], a1, Z1);
            mma16816(den[0][0], c0, Y0); mma16816(den[0][1], c0, Y1);
            mma16816(den[1][0], c1, Y0); mma16816(den[1][1], c1, Y1);
        }
    }

    // epilogue: score = sigmoid( (num + b1[q]) * rsqrt(den + cc) )
    const float ccv = g_cc;
#pragma unroll
    for (int mt = 0; mt < 2; ++mt) {
        const int r0 = qb + wm * 32 + mt * 16 + (lane >> 2);
        const float b1a = g_b1[r0];
        const float b1b = g_b1[r0 + 8];
#pragma unroll
        for (int nt = 0; nt < 2; ++nt) {
            const int col = ib + wn * 16 + nt * 8 + ((lane & 3) << 1);
            const float* d = num[mt][nt];
            const float* e = den[mt][nt];
            float v0 = (d[0] + b1a) * rsqrtf(fmaxf(e[0] + ccv, 1e-24f));
            float v1 = (d[1] + b1a) * rsqrtf(fmaxf(e[1] + ccv, 1e-24f));
            float v2 = (d[2] + b1b) * rsqrtf(fmaxf(e[2] + ccv, 1e-24f));
            float v3 = (d[3] + b1b) * rsqrtf(fmaxf(e[3] + ccv, 1e-24f));
            float2 p0, p1;
            p0.x = 1.f / (1.f + __expf(-v0));
            p0.y = 1.f / (1.f + __expf(-v1));
            p1.x = 1.f / (1.f + __expf(-v2));
            p1.y = 1.f / (1.f + __expf(-v3));
            *(float2*)(out + (size_t)r0 * I + col) = p0;
            *(float2*)(out + (size_t)(r0 + 8) * I + col) = p1;
        }
    }
}

// ---------------- entry ----------------
extern "C" void kernel_launch(void* const* d_in, const int* in_sizes, int n_in,
                              void* d_out, int out_size) {
    const float* query_feats      = (const float*)d_in[0];
    const float* query_img_feats  = (const float*)d_in[1];
    const float* gallery_img_feats= (const float*)d_in[2];
    const float* bn_gamma         = (const float*)d_in[3];
    const float* bn_beta          = (const float*)d_in[4];
    const float* bn_mean          = (const float*)d_in[5];
    const float* bn_var           = (const float*)d_in[6];
    float* out = (float*)d_out;

    cudaFuncSetAttribute(score_kernel,
                         cudaFuncAttributeMaxDynamicSharedMemorySize, SMEM_SCORE);

    prep_kernel<<<288, 256>>>(query_feats, query_img_feats, gallery_img_feats,
                              bn_gamma, bn_beta, bn_mean, bn_var);
    score_kernel<<<dim3(I / 64, Q / 64), 256, SMEM_SCORE>>>(out);
}

// round 14
// speedup vs baseline: 3.4200x; 1.0600x over previous
#include <cuda_runtime.h>
#include <cuda_bf16.h>
#include <math.h>
#include <cstdint>

// Problem shape (fixed by the dataset)
#define Q 256
#define I 2048
#define D 256

#define SE_INV_TEMP 5.0f     // 1/0.2
#define BN_EPS 1e-5f

// ---------------- device scratch (no allocs allowed) ----------------
__device__ __align__(16) __nv_bfloat16 g_Wb[Q * D];    // u_hat * a
__device__ __align__(16) __nv_bfloat16 g_A2b[Q * D];   // a*a
__device__ __align__(16) __nv_bfloat16 g_C2b[Q * D];   // 2*a*c
__device__ __align__(16) __nv_bfloat16 g_Yb[I * D];    // normalized gallery y
__device__ __align__(16) __nv_bfloat16 g_Y2b[I * D];   // y*y
__device__ float g_b1[Q];                              // <u_hat, c>
__device__ float g_cc;                                 // ||c||^2

// ---------------- PTX helpers (sm_80-era ops only: legal on compute_103) ----
__device__ __forceinline__ void cp16(uint32_t dst, const void* src) {
    asm volatile("cp.async.ca.shared.global [%0], [%1], 16;"
                 :: "r"(dst), "l"(src));
}
#define CP_COMMIT() asm volatile("cp.async.commit_group;" ::: "memory")
#define CP_WAIT(n)  asm volatile("cp.async.wait_group %0;" :: "n"(n) : "memory")

__device__ __forceinline__ void ldmx4(uint32_t* r, uint32_t a) {
    asm volatile("ldmatrix.sync.aligned.m8n8.x4.shared.b16 {%0,%1,%2,%3}, [%4];"
                 : "=r"(r[0]), "=r"(r[1]), "=r"(r[2]), "=r"(r[3]) : "r"(a));
}

__device__ __forceinline__ void mma16816(float* d, const uint32_t* a,
                                         const uint32_t* b) {
    asm volatile(
        "mma.sync.aligned.m16n8k16.row.col.f32.bf16.bf16.f32 "
        "{%0,%1,%2,%3}, {%4,%5,%6,%7}, {%8,%9}, {%0,%1,%2,%3};"
        : "+f"(d[0]), "+f"(d[1]), "+f"(d[2]), "+f"(d[3])
        : "r"(a[0]), "r"(a[1]), "r"(a[2]), "r"(a[3]), "r"(b[0]), "r"(b[1]));
}

// per-group named barrier (group g: threads g*256..g*256+255)
__device__ __forceinline__ void group_bar(int id) {
    asm volatile("bar.sync %0, 256;" :: "r"(id) : "memory");
}

// ---------------- warp reduction ----------------
__device__ __forceinline__ float wsum(float v) {
#pragma unroll
    for (int o = 16; o > 0; o >>= 1) v += __shfl_xor_sync(0xffffffffu, v, o);
    return v;
}

__device__ __forceinline__ uint4 pack8_bf16(const float* v) {
    __nv_bfloat162 a = __floats2bfloat162_rn(v[0], v[1]);
    __nv_bfloat162 b = __floats2bfloat162_rn(v[2], v[3]);
    __nv_bfloat162 c = __floats2bfloat162_rn(v[4], v[5]);
    __nv_bfloat162 d = __floats2bfloat162_rn(v[6], v[7]);
    uint4 r;
    r.x = *(unsigned*)&a; r.y = *(unsigned*)&b;
    r.z = *(unsigned*)&c; r.w = *(unsigned*)&d;
    return r;
}

// ---------------- fused preprocess: warp per row ----------------
// blocks 0..31: queries (8 per block). blocks 32..287: gallery rows (8 per block).
__global__ __launch_bounds__(256) void prep_kernel(
    const float* __restrict__ xq_in, const float* __restrict__ yq_in,
    const float* __restrict__ yg_in,
    const float* __restrict__ gamma, const float* __restrict__ beta,
    const float* __restrict__ mean,  const float* __restrict__ var) {
    const int lane = threadIdx.x & 31;
    const int warp = threadIdx.x >> 5;
    const int b = blockIdx.x;
    const int d0 = lane << 3;     // 8 elements per lane

    if (b < 32) {
        const int q = (b << 3) + warp;
        float x[8], y[8], a[8], c[8];
#pragma unroll
        for (int j = 0; j < 2; ++j) {
            float4 v = *(const float4*)(xq_in + (q << 8) + d0 + 4 * j);
            x[4*j+0]=v.x; x[4*j+1]=v.y; x[4*j+2]=v.z; x[4*j+3]=v.w;
            float4 w = *(const float4*)(yq_in + (q << 8) + d0 + 4 * j);
            y[4*j+0]=w.x; y[4*j+1]=w.y; y[4*j+2]=w.z; y[4*j+3]=w.w;
        }
        float gm[8], bt[8], mn[8], vr[8];
#pragma unroll
        for (int j = 0; j < 2; ++j) {
            float4 g4 = *(const float4*)(gamma + d0 + 4 * j);
            gm[4*j+0]=g4.x; gm[4*j+1]=g4.y; gm[4*j+2]=g4.z; gm[4*j+3]=g4.w;
            float4 b4 = *(const float4*)(beta + d0 + 4 * j);
            bt[4*j+0]=b4.x; bt[4*j+1]=b4.y; bt[4*j+2]=b4.z; bt[4*j+3]=b4.w;
            float4 m4 = *(const float4*)(mean + d0 + 4 * j);
            mn[4*j+0]=m4.x; mn[4*j+1]=m4.y; mn[4*j+2]=m4.z; mn[4*j+3]=m4.w;
            float4 v4 = *(const float4*)(var + d0 + 4 * j);
            vr[4*j+0]=v4.x; vr[4*j+1]=v4.y; vr[4*j+2]=v4.z; vr[4*j+3]=v4.w;
        }

        float sx = 0.f, sy = 0.f;
#pragma unroll
        for (int k = 0; k < 8; ++k) { sx = fmaf(x[k], x[k], sx); sy = fmaf(y[k], y[k], sy); }
        const float invx = 1.f / fmaxf(sqrtf(wsum(sx)), 1e-12f);
        const float invy = 1.f / fmaxf(sqrtf(wsum(sy)), 1e-12f);

        float fq[8];
        float sf = 0.f;
#pragma unroll
        for (int k = 0; k < 8; ++k) {
            float xn = x[k] * invx;
            float gate = 1.f / (1.f + __expf(-xn * SE_INV_TEMP));
            float istd = gm[k] * rsqrtf(vr[k] + BN_EPS);
            c[k] = bt[k] - mn[k] * istd;
            a[k] = gate * istd;
            float yn = y[k] * invy;
            fq[k] = fmaf(yn, a[k], c[k]);
            sf = fmaf(fq[k], fq[k], sf);
        }
        const float invf = 1.f / fmaxf(sqrtf(wsum(sf)), 1e-12f);

        float b1p = 0.f;
        float w_[8], a2_[8], c2_[8];
#pragma unroll
        for (int k = 0; k < 8; ++k) {
            float u = fq[k] * invf;
            w_[k]  = u * a[k];
            a2_[k] = a[k] * a[k];
            c2_[k] = 2.f * a[k] * c[k];
            b1p = fmaf(u, c[k], b1p);
        }
        *(uint4*)(g_Wb  + (q << 8) + d0) = pack8_bf16(w_);
        *(uint4*)(g_A2b + (q << 8) + d0) = pack8_bf16(a2_);
        *(uint4*)(g_C2b + (q << 8) + d0) = pack8_bf16(c2_);

        float b1 = wsum(b1p);
        if (lane == 0) g_b1[q] = b1;
        if (q == 0) {
            float ccp = 0.f;
#pragma unroll
            for (int k = 0; k < 8; ++k) ccp = fmaf(c[k], c[k], ccp);
            float cc = wsum(ccp);
            if (lane == 0) g_cc = cc;
        }
    } else {
        const int i = ((b - 32) << 3) + warp;
        float v[8];
        float s = 0.f;
#pragma unroll
        for (int j = 0; j < 2; ++j) {
            float4 v4 = *(const float4*)(yg_in + (i << 8) + d0 + 4 * j);
            v[4*j+0]=v4.x; v[4*j+1]=v4.y; v[4*j+2]=v4.z; v[4*j+3]=v4.w;
        }
#pragma unroll
        for (int k = 0; k < 8; ++k) s = fmaf(v[k], v[k], s);
        const float inv = 1.f / fmaxf(sqrtf(wsum(s)), 1e-12f);
        float yn[8], y2[8];
#pragma unroll
        for (int k = 0; k < 8; ++k) { yn[k] = v[k] * inv; y2[k] = yn[k] * yn[k]; }
        *(uint4*)(g_Yb  + (i << 8) + d0) = pack8_bf16(yn);
        *(uint4*)(g_Y2b + (i << 8) + d0) = pack8_bf16(y2);
    }
}

// ---------------- main: HMMA split-K triple-GEMM + sigmoid ------------
// CTA tile 64q x 64i, grid 32x4 = 128 CTAs (one wave), 512 threads (16 warps).
// Split-K: warp group 0 (warps 0-7) does K[0,128), group 1 (warps 8-15) does
// K[128,256). Within a group, warps tile 2m x 4n, warp tile 32q x 16i (as R13).
// Each group fills ONLY its own two K-chunks via cp.async (so its wait_group
// covers all producers of what it reads), synced by per-group named barriers.
// After compute, group 1 spills partial accumulators to smem; group 0 merges
// and runs the sigmoid epilogue.
// Row stride 144B: 16B-aligned (cp.async) and conflict-free for ldmatrix.
#define BK 64
#define NCH (D / BK)            // 4
#define SRL 144                 // row stride bytes
#define MATB (64 * SRL)         // 9216
#define BUFB (5 * MATB)         // 46080
#define SMEM_SCORE (NCH * BUFB) // 184320

__global__ __launch_bounds__(512) void score_kernel(float* __restrict__ out) {
    extern __shared__ __align__(16) char smem[];

    const int tid = threadIdx.x;
    const int wid = tid >> 5;
    const int lane = tid & 31;
    const int kh = wid >> 3;         // k-group 0/1
    const int wg = wid & 7;          // warp within group
    const int wm = wg & 1;
    const int wn = wg >> 1;
    const int qb = blockIdx.y << 6;
    const int ib = blockIdx.x << 6;

    const uint32_t sb0 = (uint32_t)__cvta_generic_to_shared(&smem[0]);

    // cp.async mapping: per chunk per matrix 512 16B-units, 2 per group-thread.
    const int tg = tid & 255;        // thread index within group
    const int u0 = tg, u1 = tg + 256;
    const int r0_ = u0 >> 3, c0_ = u0 & 7;
    const int r1_ = u1 >> 3, c1_ = u1 & 7;

#define LOAD_CHUNK(ch) do {                                                   \
        const int kc_ = (ch) * BK;                                            \
        const uint32_t db_ = sb0 + (ch) * BUFB;                               \
        const uint32_t dA_ = db_ + r0_ * SRL + c0_ * 16;                      \
        const uint32_t dB_ = db_ + r1_ * SRL + c1_ * 16;                      \
        const int sA_ = r0_ * D + kc_ + c0_ * 8;                              \
        const int sB_ = r1_ * D + kc_ + c1_ * 8;                              \
        cp16(dA_ + 0 * MATB, g_Wb  + qb * D + sA_);                           \
        cp16(dB_ + 0 * MATB, g_Wb  + qb * D + sB_);                           \
        cp16(dA_ + 1 * MATB, g_A2b + qb * D + sA_);                           \
        cp16(dB_ + 1 * MATB, g_A2b + qb * D + sB_);                           \
        cp16(dA_ + 2 * MATB, g_C2b + qb * D + sA_);                           \
        cp16(dB_ + 2 * MATB, g_C2b + qb * D + sB_);                           \
        cp16(dA_ + 3 * MATB, g_Yb  + ib * D + sA_);                           \
        cp16(dB_ + 3 * MATB, g_Yb  + ib * D + sB_);                           \
        cp16(dA_ + 4 * MATB, g_Y2b + ib * D + sA_);                           \
        cp16(dB_ + 4 * MATB, g_Y2b + ib * D + sB_);                           \
    } while (0)

    // each group loads only its own two chunks
    const int chA = 2 * kh, chB = 2 * kh + 1;
    LOAD_CHUNK(chA); CP_COMMIT();
    LOAD_CHUNK(chB); CP_COMMIT();

    // ldmatrix per-lane base addresses (chunk 0 offsets)
    const int lrow = ((lane >> 3) & 1) * 8 + (lane & 7);
    const int kb = ((lane >> 4) & 1) * 16;
    uint32_t adW[2], adA[2], adC[2];
#pragma unroll
    for (int mt = 0; mt < 2; ++mt) {
        const int r = wm * 32 + mt * 16 + lrow;
        adW[mt] = sb0 + 0 * MATB + r * SRL + kb;
        adA[mt] = sb0 + 1 * MATB + r * SRL + kb;
        adC[mt] = sb0 + 2 * MATB + r * SRL + kb;
    }
    const int rB = wn * 16 + lrow;
    const uint32_t adY  = sb0 + 3 * MATB + rB * SRL + kb;
    const uint32_t adY2 = sb0 + 4 * MATB + rB * SRL + kb;

    float num[2][2][4], den[2][2][4];
#pragma unroll
    for (int mt = 0; mt < 2; ++mt)
#pragma unroll
        for (int nt = 0; nt < 2; ++nt)
#pragma unroll
            for (int k = 0; k < 4; ++k) { num[mt][nt][k] = 0.f; den[mt][nt][k] = 0.f; }

#define COMPUTE_CHUNK(ch) do {                                                \
        const uint32_t boff = (ch) * BUFB;                                    \
_Pragma("unroll")                                                             \
        for (int kk = 0; kk < 4; ++kk) {                                      \
            const uint32_t ko = boff + kk * 32;                               \
            uint32_t w0[4], w1[4], a0[4], a1[4], c0[4], c1[4], y[4], y2[4];   \
            ldmx4(w0, adW[0] + ko); ldmx4(w1, adW[1] + ko);                   \
            ldmx4(a0, adA[0] + ko); ldmx4(a1, adA[1] + ko);                   \
            ldmx4(c0, adC[0] + ko); ldmx4(c1, adC[1] + ko);                   \
            ldmx4(y,  adY  + ko);   ldmx4(y2, adY2 + ko);                     \
            uint32_t Y0[2] = {y[0],  y[2]},  Y1[2] = {y[1],  y[3]};           \
            uint32_t Z0[2] = {y2[0], y2[2]}, Z1[2] = {y2[1], y2[3]};          \
            mma16816(num[0][0], w0, Y0); mma16816(num[0][1], w0, Y1);         \
            mma16816(num[1][0], w1, Y0); mma16816(num[1][1], w1, Y1);         \
            mma16816(den[0][0], a0, Z0); mma16816(den[0][1], a0, Z1);         \
            mma16816(den[1][0], a1, Z0); mma16816(den[1][1], a1, Z1);         \
            mma16816(den[0][0], c0, Y0); mma16816(den[0][1], c0, Y1);         \
            mma16816(den[1][0], c1, Y0); mma16816(den[1][1], c1, Y1);         \
        }                                                                     \
    } while (0)

    CP_WAIT(1);
    group_bar(kh + 1);
    COMPUTE_CHUNK(chA);
    CP_WAIT(0);
    group_bar(kh + 1);
    COMPUTE_CHUNK(chB);

    // ---- split-K merge: group 1 spills, group 0 accumulates ----
    __syncthreads();
    float* mf = (float*)smem;                 // 32KB scratch (reuses buffers)
    const int t = wg * 32 + lane;             // 0..255 within group
    if (kh == 1) {
#pragma unroll
        for (int mt = 0; mt < 2; ++mt)
#pragma unroll
            for (int nt = 0; nt < 2; ++nt)
#pragma unroll
                for (int k = 0; k < 4; ++k) {
                    const int j = (mt * 2 + nt) * 4 + k;
                    mf[j * 256 + t]        = num[mt][nt][k];
                    mf[(16 + j) * 256 + t] = den[mt][nt][k];
                }
    }
    __syncthreads();

    if (kh == 0) {
#pragma unroll
        for (int mt = 0; mt < 2; ++mt)
#pragma unroll
            for (int nt = 0; nt < 2; ++nt)
#pragma unroll
                for (int k = 0; k < 4; ++k) {
                    const int j = (mt * 2 + nt) * 4 + k;
                    num[mt][nt][k] += mf[j * 256 + t];
                    den[mt][nt][k] += mf[(16 + j) * 256 + t];
                }

        // epilogue: score = sigmoid( (num + b1[q]) * rsqrt(den + cc) )
        const float ccv = g_cc;
#pragma unroll
        for (int mt = 0; mt < 2; ++mt) {
            const int r0 = qb + wm * 32 + mt * 16 + (lane >> 2);
            const float b1a = g_b1[r0];
            const float b1b = g_b1[r0 + 8];
#pragma unroll
            for (int nt = 0; nt < 2; ++nt) {
                const int col = ib + wn * 16 + nt * 8 + ((lane & 3) << 1);
                const float* d = num[mt][nt];
                const float* e = den[mt][nt];
                float v0 = (d[0] + b1a) * rsqrtf(fmaxf(e[0] + ccv, 1e-24f));
                float v1 = (d[1] + b1a) * rsqrtf(fmaxf(e[1] + ccv, 1e-24f));
                float v2 = (d[2] + b1b) * rsqrtf(fmaxf(e[2] + ccv, 1e-24f));
                float v3 = (d[3] + b1b) * rsqrtf(fmaxf(e[3] + ccv, 1e-24f));
                float2 p0, p1;
                p0.x = 1.f / (1.f + __expf(-v0));
                p0.y = 1.f / (1.f + __expf(-v1));
                p1.x = 1.f / (1.f + __expf(-v2));
                p1.y = 1.f / (1.f + __expf(-v3));
                *(float2*)(out + (size_t)r0 * I + col) = p0;
                *(float2*)(out + (size_t)(r0 + 8) * I + col) = p1;
            }
        }
    }
}

// ---------------- entry ----------------
extern "C" void kernel_launch(void* const* d_in, const int* in_sizes, int n_in,
                              void* d_out, int out_size) {
    const float* query_feats      = (const float*)d_in[0];
    const float* query_img_feats  = (const float*)d_in[1];
    const float* gallery_img_feats= (const float*)d_in[2];
    const float* bn_gamma         = (const float*)d_in[3];
    const float* bn_beta          = (const float*)d_in[4];
    const float* bn_mean          = (const float*)d_in[5];
    const float* bn_var           = (const float*)d_in[6];
    float* out = (float*)d_out;

    cudaFuncSetAttribute(score_kernel,
                         cudaFuncAttributeMaxDynamicSharedMemorySize, SMEM_SCORE);

    prep_kernel<<<288, 256>>>(query_feats, query_img_feats, gallery_img_feats,
                              bn_gamma, bn_beta, bn_mean, bn_var);
    score_kernel<<<dim3(I / 64, Q / 64), 512, SMEM_SCORE>>>(out);
}